// round 1
// baseline (speedup 1.0000x reference)
#include <cuda_runtime.h>
#include <cuda_bf16.h>

// Problem: corr[b,n] = (1/(H*W)) * sum_{h,w} act[b,h,w] * exp(-(eh[h,n] + ew[w,n]))
// B=8, H=W=128, N=4096 (=64x64 output grid).
//
// Separable factorization: exp(-(eh+ew)) = Eh[h,n] * Ew[w,n].
// Kernel 1 builds Eh (scaled by 1/16384) and Ew tables (128 x 4096 each).
// Kernel 2: corr[b,n] = sum_h Eh[h,n] * ( sum_w act[b,h,w] * Ew[w,n] )
//   -> a 128x64x128 register-tiled FP32 GEMM per (b, n-tile) block with the
//      Eh-weighted h-reduction fused into the epilogue.

#define HDIM 128
#define NPTS 4096
#define NT   64     // n-tile per block
#define KC   16     // w chunk

// Static device scratch (allocation-free).
__device__ float g_Eh[HDIM * NPTS];
__device__ float g_Ew[HDIM * NPTS];

// ---------------------------------------------------------------------------
// Kernel 1: Gaussian factor tables.
// thread idx -> (i, n): i = idx >> 12 (grid coord), n = idx & 4095.
// Writes are coalesced along n.
// ---------------------------------------------------------------------------
__global__ __launch_bounds__(256) void gauss_tables_kernel(
    const float* __restrict__ mu,     // [N,2]
    const float* __restrict__ sigma)  // [N,2]
{
    const int idx = blockIdx.x * 256 + threadIdx.x;   // 0 .. 128*4096-1
    const int i = idx >> 12;          // 0..127  (grid position)
    const int n = idx & (NPTS - 1);   // 0..4095

    const float g = (float)i * (1.0f / 128.0f);

    const float2 m = ((const float2*)mu)[n];
    const float2 s = ((const float2*)sigma)[n];

    const float inv0 = 1.0f / (2.0f * s.x * s.x);
    const float inv1 = 1.0f / (2.0f * s.y * s.y);

    const float d0 = g - m.x;
    const float d1 = g - m.y;

    // Fold the 1/(H*W) normalization into Eh.
    g_Eh[i * NPTS + n] = __expf(-(d0 * d0 * inv0)) * (1.0f / 16384.0f);
    g_Ew[i * NPTS + n] = __expf(-(d1 * d1 * inv1));
}

// ---------------------------------------------------------------------------
// Kernel 2: fused contraction.
// Block = (n-tile of 64, batch b). 256 threads = 16(tx: n) x 16(ty: h).
// Per-thread register tile: 8 h-rows x 4 n-cols.
// Main loop: U[h][n'] += act[b,h,w] * Ew[w,n']   over w in chunks of 16.
// Epilogue:  corr[n'] = sum_h Eh[h,n'] * U[h][n'], cross-thread reduced over ty.
// ---------------------------------------------------------------------------
__global__ __launch_bounds__(256) void corr_kernel(
    const float* __restrict__ act,    // [8,128,128]
    float* __restrict__ out)          // [8,4096]
{
    __shared__ float sEh[HDIM * NT];      // [h][n']          32 KB
    __shared__ float sAct[KC * HDIM];     // [w][h] TRANSPOSED 8 KB (reused as reduce buf)
    __shared__ float sEw[KC * NT];        // [w][n']           4 KB

    const int b   = blockIdx.y;
    const int n0  = blockIdx.x * NT;
    const int tid = threadIdx.x;
    const int tx  = tid & 15;   // n' group: columns tx*4 .. tx*4+3
    const int ty  = tid >> 4;   // h  group: rows    ty*8 .. ty*8+7

    // Load full Eh tile once: 128 rows x 64 floats = 2048 float4.
    #pragma unroll
    for (int k = tid; k < HDIM * NT / 4; k += 256) {
        const int h = k >> 4;     // 16 float4 per row
        const int c = k & 15;
        ((float4*)sEh)[k] = *(const float4*)(&g_Eh[h * NPTS + n0 + c * 4]);
    }

    float U[8][4];
    #pragma unroll
    for (int i = 0; i < 8; i++)
        #pragma unroll
        for (int j = 0; j < 4; j++) U[i][j] = 0.0f;

    const float* actb = act + b * HDIM * HDIM;

    for (int wc = 0; wc < HDIM; wc += KC) {
        __syncthreads();

        // sAct[w][h] (transposed): 512 float4 global reads, scalar scatter to smem.
        #pragma unroll
        for (int k = tid; k < 512; k += 256) {
            const int h = k >> 2;
            const int c = k & 3;
            const float4 v = *(const float4*)(&actb[h * HDIM + wc + c * 4]);
            sAct[(c * 4 + 0) * HDIM + h] = v.x;
            sAct[(c * 4 + 1) * HDIM + h] = v.y;
            sAct[(c * 4 + 2) * HDIM + h] = v.z;
            sAct[(c * 4 + 3) * HDIM + h] = v.w;
        }
        // sEw chunk: 16 rows x 64 floats = 256 float4, 1 per thread.
        {
            const int w = tid >> 4;
            const int c = tid & 15;
            ((float4*)sEw)[tid] =
                *(const float4*)(&g_Ew[(wc + w) * NPTS + n0 + c * 4]);
        }
        __syncthreads();

        #pragma unroll
        for (int w = 0; w < KC; ++w) {
            const float4 e  = ((const float4*)(sEw + w * NT))[tx];
            const float4 a0 = ((const float4*)(sAct + w * HDIM + ty * 8))[0];
            const float4 a1 = ((const float4*)(sAct + w * HDIM + ty * 8))[1];
            const float a[8] = {a0.x, a0.y, a0.z, a0.w, a1.x, a1.y, a1.z, a1.w};
            #pragma unroll
            for (int i = 0; i < 8; i++) {
                U[i][0] += a[i] * e.x;
                U[i][1] += a[i] * e.y;
                U[i][2] += a[i] * e.z;
                U[i][3] += a[i] * e.w;
            }
        }
    }

    // Epilogue: weight by Eh and reduce over the thread's 8 h-rows.
    float4 p = make_float4(0.f, 0.f, 0.f, 0.f);
    #pragma unroll
    for (int i = 0; i < 8; i++) {
        const float4 eh = ((const float4*)(sEh + (ty * 8 + i) * NT))[tx];
        p.x += U[i][0] * eh.x;
        p.y += U[i][1] * eh.y;
        p.z += U[i][2] * eh.z;
        p.w += U[i][3] * eh.w;
    }

    // Cross-thread reduction over ty (16 partials per n' column).
    __syncthreads();                 // everyone done reading sAct
    float* red = sAct;               // reuse: need 16*64 floats = 4 KB
    ((float4*)red)[ty * 16 + tx] = p;
    __syncthreads();

    if (tid < NT) {
        float s = 0.0f;
        #pragma unroll
        for (int t = 0; t < 16; t++) s += red[t * NT + tid];
        out[b * NPTS + n0 + tid] = s;
    }
}

// ---------------------------------------------------------------------------
extern "C" void kernel_launch(void* const* d_in, const int* in_sizes, int n_in,
                              void* d_out, int out_size)
{
    const float* act   = (const float*)d_in[0];   // [8,128,128]
    const float* mu    = (const float*)d_in[1];   // [4096,2]
    const float* sigma = (const float*)d_in[2];   // [4096,2]
    float* out = (float*)d_out;                   // [8,64,64]

    gauss_tables_kernel<<<(HDIM * NPTS) / 256, 256>>>(mu, sigma);
    corr_kernel<<<dim3(NPTS / NT, 8), 256>>>(act, out);
}

// round 5
// speedup vs baseline: 2.0920x; 2.0920x over previous
#include <cuda_runtime.h>
#include <cuda_bf16.h>
#include <cstdint>

// corr[b,n] = sum_h EhT[n,h] * ( sum_w EwT[n,w] * act[b,h,w] )
// Inner GEMM on legacy tensor cores (mma.sync.m16n8k16.bf16, fp32 accum)
// with 3-pass bf16 error-split (hi/lo) for fp32-grade precision.
// Per CTA: (n-tile 64, batch b): M=64(n) x N=128(h) x K=128(w).

#define HDIM 128
#define NPTS 4096

// Pre-split operands (built by kernel 1).
__device__ __nv_bfloat16 g_AH[NPTS * HDIM];   // EwT hi  [n][w]
__device__ __nv_bfloat16 g_AL[NPTS * HDIM];   // EwT lo
__device__ __nv_bfloat16 g_BH[8 * HDIM * HDIM]; // act hi [b][h][w]
__device__ __nv_bfloat16 g_BL[8 * HDIM * HDIM]; // act lo
__device__ float g_EhT[NPTS * HDIM];          // [n][h], scaled by 1/16384

// ---------------------------------------------------------------------------
__device__ __forceinline__ uint32_t smem_to_u32(const void* p) {
    uint32_t a;
    asm("{ .reg .u64 t; cvta.to.shared.u64 t, %1; cvt.u32.u64 %0, t; }" : "=r"(a) : "l"(p));
    return a;
}
#define CP16(dst, src) \
    asm volatile("cp.async.cg.shared.global [%0], [%1], 16;" :: "r"(dst), "l"(src) : "memory")
#define CP_COMMIT() asm volatile("cp.async.commit_group;" ::: "memory")
#define CP_WAIT0()  asm volatile("cp.async.wait_group 0;" ::: "memory")

#define LDSM_X4(r0, r1, r2, r3, addr)                                          \
    asm volatile("ldmatrix.sync.aligned.m8n8.x4.shared.b16 {%0,%1,%2,%3}, [%4];" \
        : "=r"(r0), "=r"(r1), "=r"(r2), "=r"(r3) : "r"(addr))

#define MMA_BF16(c, a, b0, b1)                                                 \
    asm volatile("mma.sync.aligned.m16n8k16.row.col.f32.bf16.bf16.f32 "         \
        "{%0,%1,%2,%3},{%4,%5,%6,%7},{%8,%9},{%0,%1,%2,%3};"                    \
        : "+f"((c)[0]), "+f"((c)[1]), "+f"((c)[2]), "+f"((c)[3])                \
        : "r"((a)[0]), "r"((a)[1]), "r"((a)[2]), "r"((a)[3]), "r"(b0), "r"(b1))

// ---------------------------------------------------------------------------
// Kernel 1: build bf16 hi/lo tables + EhT. 512K threads.
//   idx -> (n = idx>>7, j = idx&127). j = w for EwT row, j = h for EhT row.
// ---------------------------------------------------------------------------
__global__ __launch_bounds__(256) void prep_kernel(
    const float* __restrict__ act, const float* __restrict__ mu,
    const float* __restrict__ sigma)
{
    const int idx = blockIdx.x * 256 + threadIdx.x;   // 0 .. 524287
    const int n = idx >> 7;
    const int j = idx & 127;
    const float g = (float)j * (1.0f / 128.0f);

    const float2 m = ((const float2*)mu)[n];
    const float2 s = ((const float2*)sigma)[n];

    // EwT[n][w] split hi/lo
    {
        const float d = g - m.y;
        const float v = __expf(-(d * d / (2.0f * s.y * s.y)));
        const __nv_bfloat16 hi = __float2bfloat16_rn(v);
        g_AH[idx] = hi;
        g_AL[idx] = __float2bfloat16_rn(v - __bfloat162float(hi));
    }
    // EhT[n][h] (fold 1/16384)
    {
        const float d = g - m.x;
        g_EhT[idx] = __expf(-(d * d / (2.0f * s.x * s.x))) * (1.0f / 16384.0f);
    }
    // act split hi/lo (first 131072 threads)
    if (idx < 8 * HDIM * HDIM) {
        const float v = act[idx];
        const __nv_bfloat16 hi = __float2bfloat16_rn(v);
        g_BH[idx] = hi;
        g_BL[idx] = __float2bfloat16_rn(v - __bfloat162float(hi));
    }
}

// ---------------------------------------------------------------------------
// Kernel 2: warp-mma GEMM + fused Eh contraction.
// Grid (64 n-tiles, 8 b), 128 threads = 4 warps (wm = warp&1 over n halves,
// wn = warp>>1 over h halves). Warp tile 32(n) x 64(h).
// K streamed in 2 chunks of 64 via cp.async. SMEM rows padded to 144B so the
// 8 ldmatrix lane-addresses hit 8 distinct 16B bank slots ((9r+u) mod 8 = r+u).
// ---------------------------------------------------------------------------
#define STRIDE 144
#define SA_BYTES (64 * STRIDE)          // 9216
#define SB_BYTES (128 * STRIDE)         // 18432
#define SMEM_REQ (2 * SA_BYTES + 2 * SB_BYTES)   // 55296

__global__ __launch_bounds__(128) void corr_mma_kernel(float* __restrict__ out)
{
    extern __shared__ char smem[];
    const uint32_t sb = smem_to_u32(smem);
    const uint32_t sAhi = sb;
    const uint32_t sAlo = sb + SA_BYTES;
    const uint32_t sBhi = sb + 2 * SA_BYTES;
    const uint32_t sBlo = sBhi + SB_BYTES;

    const int tid = threadIdx.x;
    const int wid = tid >> 5, l = tid & 31;
    const int wm = wid & 1, wn = wid >> 1;
    const int b  = blockIdx.y;
    const int n0 = blockIdx.x * 64;

    float acc[2][8][4];
    #pragma unroll
    for (int mt = 0; mt < 2; mt++)
        #pragma unroll
        for (int nt = 0; nt < 8; nt++)
            #pragma unroll
            for (int k = 0; k < 4; k++) acc[mt][nt][k] = 0.0f;

    // ldmatrix lane base addresses (row = l&15, col unit = l>>4).
    const uint32_t lrow = l & 15, lcol = (l >> 4) * 16;
    const uint32_t aRowBase = (wm * 32 + lrow) * STRIDE + lcol;
    const uint32_t bRowBase = (wn * 64 + lrow) * STRIDE + lcol;

    const __nv_bfloat16* gA_h = g_AH + n0 * HDIM;
    const __nv_bfloat16* gA_l = g_AL + n0 * HDIM;
    const __nv_bfloat16* gB_h = g_BH + b * HDIM * HDIM;
    const __nv_bfloat16* gB_l = g_BL + b * HDIM * HDIM;

    for (int c = 0; c < 2; c++) {
        const int kc = c * 64;
        __syncthreads();   // protect smem overwrite

        // Stage chunk: A 64 rows x 128B, B 128 rows x 128B (hi+lo), 16B units.
        #pragma unroll
        for (int i = tid; i < 512; i += 128) {
            const int row = i >> 3, u = i & 7;
            const uint32_t d = row * STRIDE + u * 16;
            CP16(sAhi + d, gA_h + row * HDIM + kc + u * 8);
            CP16(sAlo + d, gA_l + row * HDIM + kc + u * 8);
        }
        #pragma unroll
        for (int i = tid; i < 1024; i += 128) {
            const int row = i >> 3, u = i & 7;
            const uint32_t d = row * STRIDE + u * 16;
            CP16(sBhi + d, gB_h + row * HDIM + kc + u * 8);
            CP16(sBlo + d, gB_l + row * HDIM + kc + u * 8);
        }
        CP_COMMIT();
        CP_WAIT0();
        __syncthreads();

        #pragma unroll
        for (int ks = 0; ks < 4; ks++) {
            const uint32_t koff = ks * 32;
            uint32_t ah[2][4], al[2][4], bb[4][4];
            #pragma unroll
            for (int mt = 0; mt < 2; mt++) {
                const uint32_t ao = aRowBase + mt * (16 * STRIDE) + koff;
                LDSM_X4(ah[mt][0], ah[mt][1], ah[mt][2], ah[mt][3], sAhi + ao);
                LDSM_X4(al[mt][0], al[mt][1], al[mt][2], al[mt][3], sAlo + ao);
            }
            // B hi: Ahi*Bhi + Alo*Bhi
            #pragma unroll
            for (int p = 0; p < 4; p++) {
                const uint32_t bo = bRowBase + p * (16 * STRIDE) + koff;
                LDSM_X4(bb[p][0], bb[p][1], bb[p][2], bb[p][3], sBhi + bo);
            }
            #pragma unroll
            for (int mt = 0; mt < 2; mt++)
                #pragma unroll
                for (int p = 0; p < 4; p++) {
                    MMA_BF16(acc[mt][2 * p],     ah[mt], bb[p][0], bb[p][2]);
                    MMA_BF16(acc[mt][2 * p + 1], ah[mt], bb[p][1], bb[p][3]);
                    MMA_BF16(acc[mt][2 * p],     al[mt], bb[p][0], bb[p][2]);
                    MMA_BF16(acc[mt][2 * p + 1], al[mt], bb[p][1], bb[p][3]);
                }
            // B lo: Ahi*Blo
            #pragma unroll
            for (int p = 0; p < 4; p++) {
                const uint32_t bo = bRowBase + p * (16 * STRIDE) + koff;
                LDSM_X4(bb[p][0], bb[p][1], bb[p][2], bb[p][3], sBlo + bo);
            }
            #pragma unroll
            for (int mt = 0; mt < 2; mt++)
                #pragma unroll
                for (int p = 0; p < 4; p++) {
                    MMA_BF16(acc[mt][2 * p],     ah[mt], bb[p][0], bb[p][2]);
                    MMA_BF16(acc[mt][2 * p + 1], ah[mt], bb[p][1], bb[p][3]);
                }
        }
    }

    // Epilogue: per-thread dot with EhT, reduce over lane quad + warp pairs.
    // Thread holds D rows (wm*32 + mt*16 + rh*8 + l/4), cols (wn*64 + nt*8 + 2(l&3)+{0,1}).
    float rowsum[2][2];
    #pragma unroll
    for (int mt = 0; mt < 2; mt++)
        #pragma unroll
        for (int rh = 0; rh < 2; rh++) {
            const int rloc = wm * 32 + mt * 16 + rh * 8 + (l >> 2);
            const float* ep = g_EhT + (n0 + rloc) * HDIM + wn * 64 + 2 * (l & 3);
            float s = 0.0f;
            #pragma unroll
            for (int nt = 0; nt < 8; nt++) {
                const float2 e = *(const float2*)(ep + nt * 8);
                s += acc[mt][nt][rh * 2] * e.x + acc[mt][nt][rh * 2 + 1] * e.y;
            }
            s += __shfl_xor_sync(0xFFFFFFFF, s, 1);
            s += __shfl_xor_sync(0xFFFFFFFF, s, 2);
            rowsum[mt][rh] = s;
        }

    __syncthreads();                 // done reading tiles; reuse smem as reducer
    float* red = (float*)smem;       // [2 wn][64 rows]
    if ((l & 3) == 0) {
        #pragma unroll
        for (int mt = 0; mt < 2; mt++)
            #pragma unroll
            for (int rh = 0; rh < 2; rh++) {
                const int rloc = wm * 32 + mt * 16 + rh * 8 + (l >> 2);
                red[wn * 64 + rloc] = rowsum[mt][rh];
            }
    }
    __syncthreads();
    if (tid < 64)
        out[b * NPTS + n0 + tid] = red[tid] + red[64 + tid];
}

// ---------------------------------------------------------------------------
extern "C" void kernel_launch(void* const* d_in, const int* in_sizes, int n_in,
                              void* d_out, int out_size)
{
    const float* act   = (const float*)d_in[0];   // [8,128,128]
    const float* mu    = (const float*)d_in[1];   // [4096,2]
    const float* sigma = (const float*)d_in[2];   // [4096,2]
    float* out = (float*)d_out;                   // [8,64,64]

    // Unconditional (no static guards — harness rule). Idempotent and cheap.
    cudaFuncSetAttribute(corr_mma_kernel,
                         cudaFuncAttributeMaxDynamicSharedMemorySize, SMEM_REQ);

    prep_kernel<<<(NPTS * HDIM) / 256, 256>>>(act, mu, sigma);
    corr_mma_kernel<<<dim3(NPTS / 64, 8), 128, SMEM_REQ>>>(out);
}

// round 6
// speedup vs baseline: 3.2793x; 1.5676x over previous
#include <cuda_runtime.h>
#include <cuda_fp16.h>
#include <cstdint>

// corr[b,n] = (1/16384) * sum_h Eh[n,h] * ( sum_w EwT[n,w] * act[b,h,w] )
// Single-pass fp16 tensor-core GEMM (mma.sync.m16n8k16.f16, fp32 accum).
// fp16 rounding noise ~2^-12 per operand -> output norm rel_err ~3e-4 < 1e-3.
// Per CTA (n-tile 128, batch b): M=128(n) x N=128(h) x K=128(w). 256 CTAs,
// 2/SM -> single wave. 1/16384 applied in fp32 epilogue (fp16 would denormal).

#define HDIM 128
#define NPTS 4096

// fp16 tables built by prep kernel. 16B-aligned for cp.async.
__device__ __align__(256) __half g_A[NPTS * HDIM];     // EwT [n][w]
__device__ __align__(256) __half g_E[NPTS * HDIM];     // EhT [n][h]  (unscaled!)
__device__ __align__(256) __half g_act[8 * HDIM * HDIM]; // act [b][h][w]

// ---------------------------------------------------------------------------
__device__ __forceinline__ uint32_t smem_to_u32(const void* p) {
    uint32_t a;
    asm("{ .reg .u64 t; cvta.to.shared.u64 t, %1; cvt.u32.u64 %0, t; }" : "=r"(a) : "l"(p));
    return a;
}
#define CP16(dst, src) \
    asm volatile("cp.async.cg.shared.global [%0], [%1], 16;" :: "r"(dst), "l"(src) : "memory")
#define CP_COMMIT() asm volatile("cp.async.commit_group;" ::: "memory")
#define CP_WAIT0()  asm volatile("cp.async.wait_group 0;" ::: "memory")

#define LDSM_X4(r0, r1, r2, r3, addr)                                          \
    asm volatile("ldmatrix.sync.aligned.m8n8.x4.shared.b16 {%0,%1,%2,%3}, [%4];" \
        : "=r"(r0), "=r"(r1), "=r"(r2), "=r"(r3) : "r"(addr))

#define MMA_F16(c, a, b0, b1)                                                  \
    asm volatile("mma.sync.aligned.m16n8k16.row.col.f32.f16.f16.f32 "           \
        "{%0,%1,%2,%3},{%4,%5,%6,%7},{%8,%9},{%0,%1,%2,%3};"                    \
        : "+f"((c)[0]), "+f"((c)[1]), "+f"((c)[2]), "+f"((c)[3])                \
        : "r"((a)[0]), "r"((a)[1]), "r"((a)[2]), "r"((a)[3]), "r"(b0), "r"(b1))

// ---------------------------------------------------------------------------
// Kernel 1: fp16 factor tables. idx -> (n = idx>>7, j = idx&127).
// ---------------------------------------------------------------------------
__global__ __launch_bounds__(256) void prep_kernel(
    const float* __restrict__ act, const float* __restrict__ mu,
    const float* __restrict__ sigma)
{
    const int idx = blockIdx.x * 256 + threadIdx.x;   // 0 .. 524287
    const int n = idx >> 7;
    const int j = idx & 127;
    const float g = (float)j * (1.0f / 128.0f);

    const float2 m = ((const float2*)mu)[n];
    const float2 s = ((const float2*)sigma)[n];

    const float dy = g - m.y;   // EwT[n][w]
    g_A[idx] = __float2half_rn(__expf(-(dy * dy / (2.0f * s.y * s.y))));
    const float dx = g - m.x;   // EhT[n][h], NO scale (fp16 denormal hazard)
    g_E[idx] = __float2half_rn(__expf(-(dx * dx / (2.0f * s.x * s.x))));

    if (idx < 8 * HDIM * HDIM)
        g_act[idx] = __float2half_rn(act[idx]);
}

// ---------------------------------------------------------------------------
// Kernel 2: single-pass fp16 warp-mma GEMM + fused Eh contraction.
// Grid (32 n-tiles, 8 b), 256 threads = 8 warps: wm = wid&3 (n blocks of 32),
// wn = wid>>2 (h halves of 64). Warp tile 32(n) x 64(h). Full K=128 staged
// once. Rows padded to 272B = 17*16 so ldmatrix lane addrs are conflict-free
// ((17r+u) mod 8 = r+u).
// ---------------------------------------------------------------------------
#define NSTRIDE 272
#define TAB_BYTES (128 * NSTRIDE)             // 34816
#define SMEM_REQ  (3 * TAB_BYTES)             // 104448

__global__ __launch_bounds__(256, 2) void corr_mma_kernel(float* __restrict__ out)
{
    extern __shared__ char smem[];
    const uint32_t sb = smem_to_u32(smem);
    const uint32_t sA = sb;                  // EwT  [n][w]
    const uint32_t sB = sb + TAB_BYTES;      // act  [h][w]
    const uint32_t sE = sb + 2 * TAB_BYTES;  // EhT  [n][h]

    const int tid = threadIdx.x;
    const int wid = tid >> 5, l = tid & 31;
    const int wm = wid & 3, wn = wid >> 2;
    const int b  = blockIdx.y;
    const int n0 = blockIdx.x * 128;

    // Stage all three 128x256B tables (16B chunks, 24 cp.async per thread).
    const __half* gA = g_A + n0 * HDIM;
    const __half* gB = g_act + b * HDIM * HDIM;
    const __half* gE = g_E + n0 * HDIM;
    #pragma unroll
    for (int i = tid; i < 2048; i += 256) {
        const int r = i >> 4, u = i & 15;
        const uint32_t d = r * NSTRIDE + u * 16;
        const int so = r * HDIM + u * 8;
        CP16(sA + d, gA + so);
        CP16(sB + d, gB + so);
        CP16(sE + d, gE + so);
    }
    CP_COMMIT();
    CP_WAIT0();
    __syncthreads();

    float acc[2][8][4];
    #pragma unroll
    for (int mt = 0; mt < 2; mt++)
        #pragma unroll
        for (int nt = 0; nt < 8; nt++)
            #pragma unroll
            for (int k = 0; k < 4; k++) acc[mt][nt][k] = 0.0f;

    const uint32_t lrow = l & 15, lcol = (l >> 4) * 16;
    const uint32_t aBase = sA + (wm * 32 + lrow) * NSTRIDE + lcol;
    const uint32_t bBase = sB + (wn * 64 + lrow) * NSTRIDE + lcol;

    #pragma unroll
    for (int ks = 0; ks < 8; ks++) {
        const uint32_t koff = ks * 32;
        uint32_t ah[2][4], bb[4][4];
        #pragma unroll
        for (int mt = 0; mt < 2; mt++)
            LDSM_X4(ah[mt][0], ah[mt][1], ah[mt][2], ah[mt][3],
                    aBase + mt * (16 * NSTRIDE) + koff);
        #pragma unroll
        for (int p = 0; p < 4; p++)
            LDSM_X4(bb[p][0], bb[p][1], bb[p][2], bb[p][3],
                    bBase + p * (16 * NSTRIDE) + koff);
        #pragma unroll
        for (int mt = 0; mt < 2; mt++)
            #pragma unroll
            for (int p = 0; p < 4; p++) {
                MMA_F16(acc[mt][2 * p],     ah[mt], bb[p][0], bb[p][2]);
                MMA_F16(acc[mt][2 * p + 1], ah[mt], bb[p][1], bb[p][3]);
            }
    }

    // Epilogue: thread's D rows = wm*32 + mt*16 + rh*8 + l/4 (n),
    // cols = wn*64 + nt*8 + 2(l&3)+{0,1} (h). Dot with EhT from smem (half2),
    // quad-shuffle, then cross-(wn)-warp smem reduce.
    float rowsum[2][2];
    #pragma unroll
    for (int mt = 0; mt < 2; mt++)
        #pragma unroll
        for (int rh = 0; rh < 2; rh++) {
            const int nloc = wm * 32 + mt * 16 + rh * 8 + (l >> 2);
            const char* eRow = smem + 2 * TAB_BYTES + nloc * NSTRIDE
                             + (wn * 64 + 2 * (l & 3)) * 2;
            float s = 0.0f;
            #pragma unroll
            for (int nt = 0; nt < 8; nt++) {
                const float2 ef = __half22float2(*(const __half2*)(eRow + nt * 16));
                s += acc[mt][nt][rh * 2] * ef.x + acc[mt][nt][rh * 2 + 1] * ef.y;
            }
            s += __shfl_xor_sync(0xFFFFFFFF, s, 1);
            s += __shfl_xor_sync(0xFFFFFFFF, s, 2);
            rowsum[mt][rh] = s;
        }

    __syncthreads();                 // tiles dead; reuse smem as reducer
    float* red = (float*)smem;       // [2 wn][128 n] = 1 KB
    if ((l & 3) == 0) {
        #pragma unroll
        for (int mt = 0; mt < 2; mt++)
            #pragma unroll
            for (int rh = 0; rh < 2; rh++) {
                const int nloc = wm * 32 + mt * 16 + rh * 8 + (l >> 2);
                red[wn * 128 + nloc] = rowsum[mt][rh];
            }
    }
    __syncthreads();
    if (tid < 128)
        out[b * NPTS + n0 + tid] =
            (red[tid] + red[128 + tid]) * 6.103515625e-05f;  // 1/16384
}

// ---------------------------------------------------------------------------
extern "C" void kernel_launch(void* const* d_in, const int* in_sizes, int n_in,
                              void* d_out, int out_size)
{
    const float* act   = (const float*)d_in[0];   // [8,128,128]
    const float* mu    = (const float*)d_in[1];   // [4096,2]
    const float* sigma = (const float*)d_in[2];   // [4096,2]
    float* out = (float*)d_out;                   // [8,64,64]

    cudaFuncSetAttribute(corr_mma_kernel,
                         cudaFuncAttributeMaxDynamicSharedMemorySize, SMEM_REQ);

    prep_kernel<<<(NPTS * HDIM) / 256, 256>>>(act, mu, sigma);
    corr_mma_kernel<<<dim3(NPTS / 128, 8), 256, SMEM_REQ>>>(out);
}